// round 5
// baseline (speedup 1.0000x reference)
#include <cuda_runtime.h>
#include <cuda_bf16.h>
#include <cstdint>

#define HD      50
#define BT      32          // batches per block
#define TB      16          // batches per team
#define TT      512
#define NTH     448         // 2 teams x 7 warps
#define TEAMTH  224
#define HSTR    36          // duplicated-h row stride (32 data + 4 pad floats)

// smem float offsets
#define SM_W0   0           // [50][200]  gate-interleaved  (10000)
#define SM_W1   10000       // [100][200] gate-interleaved  (20000)
#define SM_HD0  30000       // layer0 h, dup'd: [team][buf][50][36]  (2*2*1800 = 7200)
#define SM_HD1  37200       // layer1 h, dup'd                        (7200)
#define SM_TOTAL 44400      // floats -> 177600 bytes

// ---------------- packed f32x2 helpers ----------------
__device__ __forceinline__ unsigned long long dup2(float w) {
    unsigned long long r;
    asm("mov.b64 %0, {%1, %1};" : "=l"(r) : "f"(w));
    return r;
}
__device__ __forceinline__ unsigned long long pack2(float lo, float hi) {
    unsigned long long r;
    asm("mov.b64 %0, {%1, %2};" : "=l"(r) : "f"(lo), "f"(hi));
    return r;
}
__device__ __forceinline__ void fma2(unsigned long long &acc,
                                     unsigned long long a,
                                     unsigned long long b) {
    asm("fma.rn.f32x2 %0, %1, %2, %3;" : "=l"(acc) : "l"(a), "l"(b), "l"(acc));
}
__device__ __forceinline__ void unpack2(unsigned long long v, float &lo, float &hi) {
    asm("mov.b64 {%0, %1}, %2;" : "=f"(lo), "=f"(hi) : "l"(v));
}
__device__ __forceinline__ float tanhap(float x) {
    float y;
    asm("tanh.approx.f32 %0, %1;" : "=f"(y) : "f"(x));
    return y;
}
__device__ __forceinline__ float sigap(float x) {
    return 0.5f * tanhap(0.5f * x) + 0.5f;
}
__device__ __forceinline__ void team_bar(int team) {
    asm volatile("bar.sync %0, %1;" :: "r"(1 + team), "r"(TEAMTH) : "memory");
}

// dense k-chunk, gate-packed accs: acc[jp][b] over jp={gates 01, 23}, b=4 batches
// Per k: 1 LDS.128 weights (packed pairs, no MOV) + 2 LDS.128 dup'd h + 8 FFMA2.
__device__ __forceinline__ void mm_chunk(unsigned long long acc[2][4],
                                         const float* __restrict__ Wk,
                                         const float* __restrict__ hb,
                                         int u, int bs) {
#pragma unroll 5
    for (int k = 0; k < HD; k++) {
        ulonglong2 w2  = *reinterpret_cast<const ulonglong2*>(Wk + k * 200 + 4 * u);
        ulonglong2 h01 = *reinterpret_cast<const ulonglong2*>(hb + k * HSTR + 8 * bs);
        ulonglong2 h23 = *reinterpret_cast<const ulonglong2*>(hb + k * HSTR + 8 * bs + 4);
        fma2(acc[0][0], h01.x, w2.x); fma2(acc[1][0], h01.x, w2.y);
        fma2(acc[0][1], h01.y, w2.x); fma2(acc[1][1], h01.y, w2.y);
        fma2(acc[0][2], h23.x, w2.x); fma2(acc[1][2], h23.x, w2.y);
        fma2(acc[0][3], h23.y, w2.x); fma2(acc[1][3], h23.y, w2.y);
    }
}

// cell update: 4 batches; c in registers; writes 8 floats (h duplicated) to hw
__device__ __forceinline__ void cell_update(unsigned long long acc[2][4],
                                            float c[4], float* __restrict__ hw) {
    float hn[4];
#pragma unroll
    for (int b = 0; b < 4; b++) {
        float gi, gf, gg, go;
        unpack2(acc[0][b], gi, gf);
        unpack2(acc[1][b], gg, go);
        float i_ = sigap(gi), f_ = sigap(gf), g_ = tanhap(gg), o_ = sigap(go);
        float cv = f_ * c[b] + i_ * g_;
        c[b] = cv;
        hn[b] = o_ * tanhap(cv);
    }
    *reinterpret_cast<float4*>(hw)     = make_float4(hn[0], hn[0], hn[1], hn[1]);
    *reinterpret_cast<float4*>(hw + 4) = make_float4(hn[2], hn[2], hn[3], hn[3]);
}

__global__ __launch_bounds__(NTH, 1)
void lstm_fused4_kernel(const float* __restrict__ x,
                        const float* __restrict__ Wih0,
                        const float* __restrict__ Whh0,
                        const float* __restrict__ bih0,
                        const float* __restrict__ bhh0,
                        const float* __restrict__ Wih1,
                        const float* __restrict__ Whh1,
                        const float* __restrict__ bih1,
                        const float* __restrict__ bhh1,
                        const float* __restrict__ W1,
                        const float* __restrict__ b1,
                        const float* __restrict__ W2,
                        const float* __restrict__ b2,
                        const float* __restrict__ W3,
                        const float* __restrict__ b3,
                        float* __restrict__ out) {
    extern __shared__ float sm[];
    float* WT0 = sm + SM_W0;
    float* WT1 = sm + SM_W1;
    float* HD0 = sm + SM_HD0;
    float* HD1 = sm + SM_HD1;

    const int tid  = threadIdx.x;
    const int b0   = blockIdx.x * BT;
    const int team = tid / TEAMTH;        // 0 or 1
    const int ttid = tid - team * TEAMTH; // 0..223
    const bool act = (ttid < 200);
    const int u  = ttid >> 2;             // 0..49
    const int bs = ttid & 3;              // 0..3  (4 batches each)

    // ---- prologue: weights transposed + gate-interleaved ----
    for (int i = tid; i < 10000; i += NTH) {
        int r = i / HD, k = i % HD;
        int uu = r % HD, j = r / HD;
        WT0[k * 200 + 4 * uu + j] = Whh0[i];
    }
    for (int i = tid; i < 10000; i += NTH) {
        int r = i / HD, k = i % HD;
        int uu = r % HD, j = r / HD;
        WT1[k * 200 + 4 * uu + j]        = Wih1[i];
        WT1[(k + HD) * 200 + 4 * uu + j] = Whh1[i];
    }
    // zero h buffers (14400 floats)
    for (int i = tid; i < 14400; i += NTH) HD0[i] = 0.0f;

    // packed per-thread constants
    unsigned long long bias0a = 0, bias0b = 0, bias1a = 0, bias1b = 0;
    unsigned long long wx01 = 0, wx23 = 0;
    if (act) {
        bias0a = pack2(bih0[u]        + bhh0[u],        bih0[u + 50]  + bhh0[u + 50]);
        bias0b = pack2(bih0[u + 100]  + bhh0[u + 100],  bih0[u + 150] + bhh0[u + 150]);
        bias1a = pack2(bih1[u]        + bhh1[u],        bih1[u + 50]  + bhh1[u + 50]);
        bias1b = pack2(bih1[u + 100]  + bhh1[u + 100],  bih1[u + 150] + bhh1[u + 150]);
        wx01   = pack2(Wih0[u],       Wih0[u + 50]);
        wx23   = pack2(Wih0[u + 100], Wih0[u + 150]);
    }
    __syncthreads();

    // per-team h pointers
    float* h0t = HD0 + team * 3600;   // [buf*1800 + k*36 + col]
    float* h1t = HD1 + team * 3600;

    float c0[4] = {0, 0, 0, 0};
    float c1[4] = {0, 0, 0, 0};

    // x prefetch: this thread's 4 batches, one step ahead (L2-resident, tiny)
    const float* xp = x + (size_t)(b0 + team * TB + 4 * bs) * TT;
    float xf[4] = {0, 0, 0, 0};
    if (act) {
#pragma unroll
        for (int i = 0; i < 4; i++) xf[i] = xp[i * TT + 0];
    }

    for (int t = 0; t < TT; t++) {
        const int rb = t & 1;
        const int wb = rb ^ 1;

        if (act) {
            // ===== layer 0 =====
            unsigned long long acc[2][4];
#pragma unroll
            for (int b = 0; b < 4; b++) {
                unsigned long long xb = dup2(xf[b]);
                acc[0][b] = bias0a; fma2(acc[0][b], xb, wx01);
                acc[1][b] = bias0b; fma2(acc[1][b], xb, wx23);
            }
            // prefetch x for next step (consumed after 2 barriers -> latency hidden)
            {
                int tn = (t + 1) & (TT - 1);
#pragma unroll
                for (int i = 0; i < 4; i++) xf[i] = xp[i * TT + tn];
            }
            mm_chunk(acc, WT0, h0t + rb * 1800, u, bs);
            cell_update(acc, c0, h0t + wb * 1800 + u * HSTR + 8 * bs);
        }
        team_bar(team);

        if (act) {
            // ===== layer 1: new h0 (wb) + old h1 (rb) =====
            unsigned long long acc[2][4];
#pragma unroll
            for (int b = 0; b < 4; b++) { acc[0][b] = bias1a; acc[1][b] = bias1b; }
            mm_chunk(acc, WT1,            h0t + wb * 1800, u, bs);
            mm_chunk(acc, WT1 + HD * 200, h1t + rb * 1800, u, bs);
            cell_update(acc, c1, h1t + wb * 1800 + u * HSTR + 8 * bs);
        }
        team_bar(team);
    }

    __syncthreads();

    // ---- MLP head on final h1 (buffer 0, TT even); dup'd layout ----
    // h_final(k, b) = HD1[(b>>4)*3600 + k*36 + 2*(b&15)]
    float* tmp1 = WT0;              // scratch [32][33]
    float* tmp2 = WT0 + 1100;       // scratch [32][17]
    for (int item = tid; item < BT * 32; item += NTH) {
        int b = item >> 5;
        int o = item & 31;
        const float* hf = HD1 + (b >> 4) * 3600 + 2 * (b & 15);
        float s = b1[o];
#pragma unroll
        for (int k = 0; k < HD; k++) s += hf[k * HSTR] * W1[o * HD + k];
        tmp1[b * 33 + o] = fmaxf(s, 0.0f);
    }
    __syncthreads();
    for (int item = tid; item < BT * 16; item += NTH) {
        int b = item >> 4;
        int o = item & 15;
        float s = b2[o];
#pragma unroll
        for (int k = 0; k < 32; k++) s += tmp1[b * 33 + k] * W2[o * 32 + k];
        tmp2[b * 17 + o] = fmaxf(s, 0.0f);
    }
    __syncthreads();
    if (tid < BT) {
        float s = b3[0];
#pragma unroll
        for (int k = 0; k < 16; k++) s += tmp2[tid * 17 + k] * W3[k];
        out[b0 + tid] = s;
    }
}

extern "C" void kernel_launch(void* const* d_in, const int* in_sizes, int n_in,
                              void* d_out, int out_size) {
    const float* x    = (const float*)d_in[0];
    const float* Wih0 = (const float*)d_in[1];
    const float* Whh0 = (const float*)d_in[2];
    const float* bih0 = (const float*)d_in[3];
    const float* bhh0 = (const float*)d_in[4];
    const float* Wih1 = (const float*)d_in[5];
    const float* Whh1 = (const float*)d_in[6];
    const float* bih1 = (const float*)d_in[7];
    const float* bhh1 = (const float*)d_in[8];
    const float* W1   = (const float*)d_in[9];
    const float* b1   = (const float*)d_in[10];
    const float* W2   = (const float*)d_in[11];
    const float* b2   = (const float*)d_in[12];
    const float* W3   = (const float*)d_in[13];
    const float* b3   = (const float*)d_in[14];
    float* out = (float*)d_out;

    int B = in_sizes[0] / TT;
    int grid = B / BT;  // 128

    size_t smem_bytes = (size_t)SM_TOTAL * sizeof(float);  // 177600 B
    cudaFuncSetAttribute(lstm_fused4_kernel,
                         cudaFuncAttributeMaxDynamicSharedMemorySize,
                         (int)smem_bytes);

    lstm_fused4_kernel<<<grid, NTH, smem_bytes>>>(
        x, Wih0, Whh0, bih0, bhh0,
        Wih1, Whh1, bih1, bhh1,
        W1, b1, W2, b2, W3, b3, out);
}

// round 6
// speedup vs baseline: 1.5872x; 1.5872x over previous
#include <cuda_runtime.h>
#include <cuda_bf16.h>
#include <cstdint>

#define HD      50
#define BT      32          // batches per block (both teams cover all 32)
#define TT      512
#define NTH     448         // team A: warps 0-6 (layer0), team B: warps 7-13 (layer1)
#define TEAMTH  224
#define HSTR    36          // h row stride in floats
#define RINGD   8           // h0 ring depth (steps)

// smem float offsets
#define SM_W0   0           // [50][200]  gate-interleaved  (10000)
#define SM_W1   10000       // [100][200] gate-interleaved  (20000)
#define SM_H0R  30000       // h0 ring: RINGD x [50][36]    (14400)
#define SM_H1   44400       // h1 double buf: 2 x [50][36]  (3600)
#define SM_FLG  48000       // prod/cons counters (ints)
#define SM_TOTAL 48016      // floats -> 192064 bytes

// ---------------- packed f32x2 helpers ----------------
__device__ __forceinline__ unsigned long long dup2(float w) {
    unsigned long long r;
    asm("mov.b64 %0, {%1, %1};" : "=l"(r) : "f"(w));
    return r;
}
__device__ __forceinline__ unsigned long long pack2(float lo, float hi) {
    unsigned long long r;
    asm("mov.b64 %0, {%1, %2};" : "=l"(r) : "f"(lo), "f"(hi));
    return r;
}
__device__ __forceinline__ void fma2(unsigned long long &acc,
                                     unsigned long long a,
                                     unsigned long long b) {
    asm("fma.rn.f32x2 %0, %1, %2, %3;" : "=l"(acc) : "l"(a), "l"(b), "l"(acc));
}
__device__ __forceinline__ void unpack2(unsigned long long v, float &lo, float &hi) {
    asm("mov.b64 {%0, %1}, %2;" : "=f"(lo), "=f"(hi) : "l"(v));
}
__device__ __forceinline__ float tanhap(float x) {
    float y;
    asm("tanh.approx.f32 %0, %1;" : "=f"(y) : "f"(x));
    return y;
}
__device__ __forceinline__ float sigap(float x) {
    return 0.5f * tanhap(0.5f * x) + 0.5f;
}
__device__ __forceinline__ void team_bar(int id) {
    asm volatile("bar.sync %0, %1;" :: "r"(id), "r"(TEAMTH) : "memory");
}
__device__ __forceinline__ void spin_ge(volatile int* p, int want) {
    while (*p < want) { }
    asm volatile("" ::: "memory");   // no hoisting of LDS above the spin
}

// dense k-chunk (R2-proven): acc[j][p] += W[k][4u+j] * h[k][8bs + 2p..]
// 4 gates (j) x 8 batches (4 packed pairs). Per k: 3 LDS.128 + 4 MOV + 16 FFMA2.
__device__ __forceinline__ void mm_chunk(unsigned long long acc[4][4],
                                         const float* __restrict__ Wk,
                                         const float* __restrict__ hb,
                                         int u, int bs) {
#pragma unroll 5
    for (int k = 0; k < HD; k++) {
        float4 w = *reinterpret_cast<const float4*>(Wk + k * 200 + 4 * u);
        ulonglong2 ha = *reinterpret_cast<const ulonglong2*>(hb + k * HSTR + 8 * bs);
        ulonglong2 hc = *reinterpret_cast<const ulonglong2*>(hb + k * HSTR + 8 * bs + 4);
        unsigned long long w0 = dup2(w.x), w1 = dup2(w.y), w2 = dup2(w.z), w3 = dup2(w.w);
        fma2(acc[0][0], ha.x, w0); fma2(acc[0][1], ha.y, w0);
        fma2(acc[0][2], hc.x, w0); fma2(acc[0][3], hc.y, w0);
        fma2(acc[1][0], ha.x, w1); fma2(acc[1][1], ha.y, w1);
        fma2(acc[1][2], hc.x, w1); fma2(acc[1][3], hc.y, w1);
        fma2(acc[2][0], ha.x, w2); fma2(acc[2][1], ha.y, w2);
        fma2(acc[2][2], hc.x, w2); fma2(acc[2][3], hc.y, w2);
        fma2(acc[3][0], ha.x, w3); fma2(acc[3][1], ha.y, w3);
        fma2(acc[3][2], hc.x, w3); fma2(acc[3][3], hc.y, w3);
    }
}

// cell update for 8 batches; c in regs; writes 8 h floats
__device__ __forceinline__ void cell_update(unsigned long long acc[4][4],
                                            float c[8], float* __restrict__ hw) {
    float hn[8];
#pragma unroll
    for (int p = 0; p < 4; p++) {
        float il, ih, fl, fh, gl, gh, ol, oh;
        unpack2(acc[0][p], il, ih);
        unpack2(acc[1][p], fl, fh);
        unpack2(acc[2][p], gl, gh);
        unpack2(acc[3][p], ol, oh);
        {
            float i_ = sigap(il), f_ = sigap(fl), g_ = tanhap(gl), o_ = sigap(ol);
            float cv = f_ * c[2 * p] + i_ * g_;
            c[2 * p] = cv;
            hn[2 * p] = o_ * tanhap(cv);
        }
        {
            float i_ = sigap(ih), f_ = sigap(fh), g_ = tanhap(gh), o_ = sigap(oh);
            float cv = f_ * c[2 * p + 1] + i_ * g_;
            c[2 * p + 1] = cv;
            hn[2 * p + 1] = o_ * tanhap(cv);
        }
    }
    *reinterpret_cast<float4*>(hw)     = make_float4(hn[0], hn[1], hn[2], hn[3]);
    *reinterpret_cast<float4*>(hw + 4) = make_float4(hn[4], hn[5], hn[6], hn[7]);
}

__global__ __launch_bounds__(NTH, 1)
void lstm_pipe_kernel(const float* __restrict__ x,
                      const float* __restrict__ Wih0,
                      const float* __restrict__ Whh0,
                      const float* __restrict__ bih0,
                      const float* __restrict__ bhh0,
                      const float* __restrict__ Wih1,
                      const float* __restrict__ Whh1,
                      const float* __restrict__ bih1,
                      const float* __restrict__ bhh1,
                      const float* __restrict__ W1,
                      const float* __restrict__ b1,
                      const float* __restrict__ W2,
                      const float* __restrict__ b2,
                      const float* __restrict__ W3,
                      const float* __restrict__ b3,
                      float* __restrict__ out) {
    extern __shared__ float sm[];
    float* WT0  = sm + SM_W0;
    float* WT1  = sm + SM_W1;
    float* H0R  = sm + SM_H0R;   // ring slots of 1800 floats
    float* H1   = sm + SM_H1;    // 2 bufs of 1800
    volatile int* prod = (volatile int*)(sm + SM_FLG);
    volatile int* cons = (volatile int*)(sm + SM_FLG) + 1;

    const int tid  = threadIdx.x;
    const int b0   = blockIdx.x * BT;
    const int team = tid / TEAMTH;        // 0 = layer0 producer, 1 = layer1 consumer
    const int ttid = tid - team * TEAMTH;
    const bool act = (ttid < 200);
    const int u  = ttid >> 2;             // 0..49
    const int bs = ttid & 3;              // 0..3, 8 batches each

    // ---- prologue (all threads cooperate) ----
    for (int i = tid; i < 10000; i += NTH) {
        int r = i / HD, k = i % HD;
        int uu = r % HD, j = r / HD;
        WT0[k * 200 + 4 * uu + j] = Whh0[i];
    }
    for (int i = tid; i < 10000; i += NTH) {
        int r = i / HD, k = i % HD;
        int uu = r % HD, j = r / HD;
        WT1[k * 200 + 4 * uu + j]        = Wih1[i];
        WT1[(k + HD) * 200 + 4 * uu + j] = Whh1[i];
    }
    // zero ring slot RINGD-1 (h0 at t=-1) and both h1 buffers
    for (int i = tid; i < 1800; i += NTH) H0R[(RINGD - 1) * 1800 + i] = 0.0f;
    for (int i = tid; i < 3600; i += NTH) H1[i] = 0.0f;
    if (tid == 0) { *prod = 0; *cons = 0; }
    __syncthreads();

    if (team == 0) {
        // =================== TEAM A: layer-0 recurrence ===================
        unsigned long long bias0a = 0, bias0b = 0, bias0c = 0, bias0d = 0;
        unsigned long long wx0 = 0, wx1 = 0, wx2 = 0, wx3 = 0;
        float c0[8] = {0, 0, 0, 0, 0, 0, 0, 0};
        const float* xp = x + (size_t)(b0 + 8 * bs) * TT;
        float xf[8];
        if (act) {
            bias0a = dup2(bih0[u]       + bhh0[u]);
            bias0b = dup2(bih0[u + 50]  + bhh0[u + 50]);
            bias0c = dup2(bih0[u + 100] + bhh0[u + 100]);
            bias0d = dup2(bih0[u + 150] + bhh0[u + 150]);
            wx0 = dup2(Wih0[u]);       wx1 = dup2(Wih0[u + 50]);
            wx2 = dup2(Wih0[u + 100]); wx3 = dup2(Wih0[u + 150]);
#pragma unroll
            for (int i = 0; i < 8; i++) xf[i] = xp[(size_t)i * TT];
        }

        for (int t = 0; t < TT; t++) {
            const int rs = (t + RINGD - 1) & (RINGD - 1);   // slot of h0(t-1)
            const int ws = t & (RINGD - 1);                 // slot for h0(t)
            if (act) {
                unsigned long long acc[4][4];
#pragma unroll
                for (int p = 0; p < 4; p++) {
                    unsigned long long xb = pack2(xf[2 * p], xf[2 * p + 1]);
                    acc[0][p] = bias0a; fma2(acc[0][p], xb, wx0);
                    acc[1][p] = bias0b; fma2(acc[1][p], xb, wx1);
                    acc[2][p] = bias0c; fma2(acc[2][p], xb, wx2);
                    acc[3][p] = bias0d; fma2(acc[3][p], xb, wx3);
                }
                // prefetch next x (L2-resident; consumed next step)
                {
                    int tn = (t + 1) & (TT - 1);
#pragma unroll
                    for (int i = 0; i < 8; i++) xf[i] = xp[(size_t)i * TT + tn];
                }
                mm_chunk(acc, WT0, H0R + rs * 1800, u, bs);
                // ring backpressure: slot ws last used by step t-RINGD
                spin_ge(cons, t - RINGD + 1);
                cell_update(acc, c0, H0R + ws * 1800 + u * HSTR + 8 * bs);
            } else {
                spin_ge(cons, t - RINGD + 1);
            }
            team_bar(1);                 // h0(t) writes drained & team-wide done
            if (ttid == 0) *prod = t + 1;
        }
    } else {
        // =================== TEAM B: layer-1 recurrence ===================
        unsigned long long bias1a = 0, bias1b = 0, bias1c = 0, bias1d = 0;
        float c1[8] = {0, 0, 0, 0, 0, 0, 0, 0};
        if (act) {
            bias1a = dup2(bih1[u]       + bhh1[u]);
            bias1b = dup2(bih1[u + 50]  + bhh1[u + 50]);
            bias1c = dup2(bih1[u + 100] + bhh1[u + 100]);
            bias1d = dup2(bih1[u + 150] + bhh1[u + 150]);
        }

        for (int t = 0; t < TT; t++) {
            const int hs = t & (RINGD - 1);   // h0(t) slot
            const int rb = t & 1;             // h1(t-1) buffer
            const int wb = rb ^ 1;
            spin_ge(prod, t + 1);             // wait for h0(t)
            if (act) {
                unsigned long long acc[4][4];
#pragma unroll
                for (int p = 0; p < 4; p++) {
                    acc[0][p] = bias1a; acc[1][p] = bias1b;
                    acc[2][p] = bias1c; acc[3][p] = bias1d;
                }
                mm_chunk(acc, WT1,            H0R + hs * 1800, u, bs);
                mm_chunk(acc, WT1 + HD * 200, H1 + rb * 1800, u, bs);
                cell_update(acc, c1, H1 + wb * 1800 + u * HSTR + 8 * bs);
            }
            team_bar(2);                      // all reads of slot hs done
            if (ttid == 0) *cons = t + 1;
        }
    }

    __syncthreads();

    // ---- MLP head on final h1 (buffer (511&1)^1 = 0) ----
    const float* hf = H1;              // [k*HSTR + b]
    float* tmp1 = WT0;                 // scratch [32][33]
    float* tmp2 = WT0 + 1100;          // scratch [32][17]
    for (int item = tid; item < BT * 32; item += NTH) {
        int b = item >> 5;
        int o = item & 31;
        float s = b1[o];
#pragma unroll
        for (int k = 0; k < HD; k++) s += hf[k * HSTR + b] * W1[o * HD + k];
        tmp1[b * 33 + o] = fmaxf(s, 0.0f);
    }
    __syncthreads();
    for (int item = tid; item < BT * 16; item += NTH) {
        int b = item >> 4;
        int o = item & 15;
        float s = b2[o];
#pragma unroll
        for (int k = 0; k < 32; k++) s += tmp1[b * 33 + k] * W2[o * 32 + k];
        tmp2[b * 17 + o] = fmaxf(s, 0.0f);
    }
    __syncthreads();
    if (tid < BT) {
        float s = b3[0];
#pragma unroll
        for (int k = 0; k < 16; k++) s += tmp2[tid * 17 + k] * W3[k];
        out[b0 + tid] = s;
    }
}

extern "C" void kernel_launch(void* const* d_in, const int* in_sizes, int n_in,
                              void* d_out, int out_size) {
    const float* x    = (const float*)d_in[0];
    const float* Wih0 = (const float*)d_in[1];
    const float* Whh0 = (const float*)d_in[2];
    const float* bih0 = (const float*)d_in[3];
    const float* bhh0 = (const float*)d_in[4];
    const float* Wih1 = (const float*)d_in[5];
    const float* Whh1 = (const float*)d_in[6];
    const float* bih1 = (const float*)d_in[7];
    const float* bhh1 = (const float*)d_in[8];
    const float* W1   = (const float*)d_in[9];
    const float* b1   = (const float*)d_in[10];
    const float* W2   = (const float*)d_in[11];
    const float* b2   = (const float*)d_in[12];
    const float* W3   = (const float*)d_in[13];
    const float* b3   = (const float*)d_in[14];
    float* out = (float*)d_out;

    int B = in_sizes[0] / TT;
    int grid = B / BT;  // 128

    size_t smem_bytes = (size_t)SM_TOTAL * sizeof(float);  // 192064 B
    cudaFuncSetAttribute(lstm_pipe_kernel,
                         cudaFuncAttributeMaxDynamicSharedMemorySize,
                         (int)smem_bytes);

    lstm_pipe_kernel<<<grid, NTH, smem_bytes>>>(
        x, Wih0, Whh0, bih0, bhh0,
        Wih1, Whh1, bih1, bhh1,
        W1, b1, W2, b2, W3, b3, out);
}